// round 6
// baseline (speedup 1.0000x reference)
#include <cuda_runtime.h>
#include <math.h>

// ---------------- problem constants ----------------
constexpr int Nn   = 50000;
constexpr int Ee   = 800000;
constexpr int H    = 128;
constexpr int KE1  = 263;      // 2H + 7 (edge MLP layer-1 fan-in)
constexpr int KN1  = 256;      // 2H (node MLP layer-1 fan-in)
constexpr int TILE = 128;      // rows (edges/nodes) per block
constexpr int KC   = 64;       // k-chunk
constexpr int MST  = 132;      // padded stride of the 128x128 smem tile
constexpr int SMEM_FLOATS = TILE * MST + KC * H;   // Ms/Ag union + Bs
constexpr int SMEM_BYTES  = SMEM_FLOATS * 4;       // 100352 B

// ---------------- scratch (device globals: no allocs allowed) ----------------
__device__ float g_agg[(size_t)Nn * H];   // segment-sum accumulator
__device__ float g_ea [(size_t)Ee * 4];   // edge_attr = [rel_pos(3), dist]

// ---------------- GEMM building blocks ----------------
__device__ __forceinline__ void init_bias(const float* __restrict__ b, int colb,
                                          float acc[8][8]) {
    float4 c0 = *(const float4*)(b + colb);
    float4 c1 = *(const float4*)(b + colb + 4);
    float bb[8] = {c0.x, c0.y, c0.z, c0.w, c1.x, c1.y, c1.z, c1.w};
#pragma unroll
    for (int i = 0; i < 8; ++i)
#pragma unroll
        for (int j = 0; j < 8; ++j) acc[i][j] = bb[j];
}

// A: row-major [TILE][astride], Bs: [KC][H]; acc += A[rowb..+7][0..KC) * Bs
__device__ __forceinline__ void mma_chunk(const float* __restrict__ A, int astride,
                                          const float* __restrict__ Bs,
                                          int rowb, int colb, float acc[8][8]) {
#pragma unroll 4
    for (int k = 0; k < KC; ++k) {
        float a[8];
#pragma unroll
        for (int i = 0; i < 8; ++i) a[i] = A[(rowb + i) * astride + k];
        float4 b0 = *(const float4*)(Bs + k * H + colb);
        float4 b1 = *(const float4*)(Bs + k * H + colb + 4);
        float b[8] = {b0.x, b0.y, b0.z, b0.w, b1.x, b1.y, b1.z, b1.w};
#pragma unroll
        for (int i = 0; i < 8; ++i)
#pragma unroll
            for (int j = 0; j < 8; ++j)
                acc[i][j] = fmaf(a[i], b[j], acc[i][j]);
    }
}

// stage weight chunk W[k0..k0+KC) x [H] into Bs, zero-fill beyond K
__device__ __forceinline__ void load_B(float* __restrict__ Bs,
                                       const float* __restrict__ W,
                                       int k0, int K, int tid) {
#pragma unroll
    for (int it = 0; it < (KC * H) / 256; ++it) {
        int idx = it * 256 + tid;
        int f = idx & (H - 1);
        int k = idx >> 7;
        int kg = k0 + k;
        Bs[k * H + f] = (kg < K) ? W[kg * H + f] : 0.f;
    }
}

template <bool RELU>
__device__ __forceinline__ void store_tile(float* __restrict__ Ms, int rowb, int colb,
                                           const float acc[8][8]) {
#pragma unroll
    for (int i = 0; i < 8; ++i) {
        float4 v0, v1;
        v0.x = RELU ? fmaxf(acc[i][0], 0.f) : acc[i][0];
        v0.y = RELU ? fmaxf(acc[i][1], 0.f) : acc[i][1];
        v0.z = RELU ? fmaxf(acc[i][2], 0.f) : acc[i][2];
        v0.w = RELU ? fmaxf(acc[i][3], 0.f) : acc[i][3];
        v1.x = RELU ? fmaxf(acc[i][4], 0.f) : acc[i][4];
        v1.y = RELU ? fmaxf(acc[i][5], 0.f) : acc[i][5];
        v1.z = RELU ? fmaxf(acc[i][6], 0.f) : acc[i][6];
        v1.w = RELU ? fmaxf(acc[i][7], 0.f) : acc[i][7];
        *(float4*)(Ms + (rowb + i) * MST + colb)     = v0;
        *(float4*)(Ms + (rowb + i) * MST + colb + 4) = v1;
    }
}

// hidden layer: acc = Ms(128-wide) @ W + b, two KC chunks.
// Caller must have __syncthreads()'d after the last write to Ms.
__device__ __forceinline__ void hidden_layer(const float* __restrict__ Ms,
                                             float* __restrict__ Bs,
                                             const float* __restrict__ W,
                                             const float* __restrict__ b,
                                             int rowb, int colb, int tid,
                                             float acc[8][8]) {
    init_bias(b, colb, acc);
#pragma unroll
    for (int c = 0; c < 2; ++c) {
        if (c) __syncthreads();             // protect Bs chunk-0 readers
        load_B(Bs, W, c * KC, H, tid);
        __syncthreads();
        mma_chunk(Ms + c * KC, MST, Bs, rowb, colb, acc);
    }
}

// ---------------- prologue kernels ----------------
__global__ void k_eattr(const float* __restrict__ pos,
                        const int* __restrict__ erow, const int* __restrict__ ecol) {
    int e = blockIdx.x * blockDim.x + threadIdx.x;
    if (e >= Ee) return;
    int r = erow[e], c = ecol[e];
    float dx = pos[c * 3 + 0] - pos[r * 3 + 0];
    float dy = pos[c * 3 + 1] - pos[r * 3 + 1];
    float dz = pos[c * 3 + 2] - pos[r * 3 + 2];
    float d = sqrtf(dx * dx + dy * dy + dz * dz);
    *(float4*)(g_ea + (size_t)e * 4) = make_float4(dx, dy, dz, d);
}

__global__ void k_h0(const float* __restrict__ x, const float* __restrict__ Win,
                     const float* __restrict__ bin, float* __restrict__ h) {
    __shared__ float xs[16];
    int n = blockIdx.x, j = threadIdx.x;
    if (j < 16) xs[j] = x[n * 16 + j];
    __syncthreads();
    float a = bin[j];
#pragma unroll
    for (int k = 0; k < 16; ++k) a = fmaf(xs[k], Win[k * H + j], a);
    h[n * H + j] = a;
}

__global__ void k_zero() {
    int i = blockIdx.x * blockDim.x + threadIdx.x;
    ((float4*)g_agg)[i] = make_float4(0.f, 0.f, 0.f, 0.f);
}

// ---------------- fused edge MLP (3 layers) + atomic segment-sum ----------------
__global__ void __launch_bounds__(256, 2)
k_edge(const float* __restrict__ h,
       const int* __restrict__ erow, const int* __restrict__ ecol,
       const float* __restrict__ W1, const float* __restrict__ b1,
       const float* __restrict__ W2, const float* __restrict__ b2,
       const float* __restrict__ W3, const float* __restrict__ b3) {
    extern __shared__ float sm[];
    float* Ms = sm;                 // [TILE][MST]  (aliases Ag; disjoint lifetimes)
    float* Ag = sm;                 // [TILE][KC]   gather chunk
    float* Bs = sm + TILE * MST;    // [KC][H]      weight chunk

    const int tid  = threadIdx.x;
    const int tx   = tid & 15, ty = tid >> 4;
    const int rowb = ty * 8, colb = tx * 8;
    const int e0   = blockIdx.x * TILE;

    float acc[8][8];

    // -------- layer 1: K = 263, gathered on the fly --------
    init_bias(b1, colb, acc);
    for (int k0 = 0; k0 < KE1; k0 += KC) {          // 5 chunks (last padded w/ zeros)
        if (k0) __syncthreads();                    // protect Ag/Bs readers
#pragma unroll 4
        for (int it = 0; it < (TILE * KC) / 256; ++it) {
            int idx = it * 256 + tid;
            int e = idx >> 6;                       // edge within tile
            int k = idx & (KC - 1);
            int kg = k0 + k;
            int ge = e0 + e;
            float v = 0.f;
            if (kg < 128)        v = h[ecol[ge] * H + kg];
            else if (kg < 256)   v = h[erow[ge] * H + (kg - 128)];
            else if (kg < 260)   v = g_ea[(size_t)ge * 4 + (kg - 256)];
            else if (kg < KE1) { int d = kg - 260;
                                 v = h[ecol[ge] * H + 3 + d] - h[erow[ge] * H + 3 + d]; }
            Ag[e * KC + k] = v;
        }
        load_B(Bs, W1, k0, KE1, tid);
        __syncthreads();
        mma_chunk(Ag, KC, Bs, rowb, colb, acc);
    }
    __syncthreads();
    store_tile<true>(Ms, rowb, colb, acc);          // m1 = relu(...)
    __syncthreads();

    // -------- layer 2 --------
    hidden_layer(Ms, Bs, W2, b2, rowb, colb, tid, acc);
    __syncthreads();
    store_tile<true>(Ms, rowb, colb, acc);          // m2 = relu(...)
    __syncthreads();

    // -------- layer 3 (no relu) + atomic scatter into agg[col] --------
    hidden_layer(Ms, Bs, W3, b3, rowb, colb, tid, acc);
#pragma unroll
    for (int i = 0; i < 8; ++i) {
        int tgt = ecol[e0 + rowb + i];
        float* dst = g_agg + (size_t)tgt * H + colb;
#pragma unroll
        for (int j = 0; j < 8; ++j) atomicAdd(dst + j, acc[i][j]);
    }
}

// ---------------- fused node MLP (3 layers) + residual + LayerNorm ----------------
__global__ void __launch_bounds__(256, 2)
k_node(float* __restrict__ h,
       const float* __restrict__ W1, const float* __restrict__ b1,
       const float* __restrict__ W2, const float* __restrict__ b2,
       const float* __restrict__ W3, const float* __restrict__ b3,
       const float* __restrict__ lng, const float* __restrict__ lnb) {
    extern __shared__ float sm[];
    float* Ms = sm;
    float* Ag = sm;
    float* Bs = sm + TILE * MST;

    const int tid  = threadIdx.x;
    const int tx   = tid & 15, ty = tid >> 4;
    const int rowb = ty * 8, colb = tx * 8;
    const int n0   = blockIdx.x * TILE;

    float acc[8][8];

    // -------- layer 1: K = 256, input = [h | agg] --------
    init_bias(b1, colb, acc);
    for (int k0 = 0; k0 < KN1; k0 += KC) {          // 4 chunks, no padding
        if (k0) __syncthreads();
#pragma unroll 4
        for (int it = 0; it < (TILE * KC) / 256; ++it) {
            int idx = it * 256 + tid;
            int e = idx >> 6;
            int k = idx & (KC - 1);
            int kg = k0 + k;
            int node = n0 + e;
            if (node >= Nn) node = Nn - 1;          // clamp; result discarded later
            float v = (kg < 128) ? h[node * H + kg]
                                 : g_agg[(size_t)node * H + (kg - 128)];
            Ag[e * KC + k] = v;
        }
        load_B(Bs, W1, k0, KN1, tid);
        __syncthreads();
        mma_chunk(Ag, KC, Bs, rowb, colb, acc);
    }
    __syncthreads();
    store_tile<true>(Ms, rowb, colb, acc);
    __syncthreads();

    // -------- layer 2 --------
    hidden_layer(Ms, Bs, W2, b2, rowb, colb, tid, acc);
    __syncthreads();
    store_tile<true>(Ms, rowb, colb, acc);
    __syncthreads();

    // -------- layer 3 (no relu) + residual into Ms --------
    hidden_layer(Ms, Bs, W3, b3, rowb, colb, tid, acc);
    __syncthreads();                                // all Ms (m2) reads done
#pragma unroll
    for (int i = 0; i < 8; ++i) {
        int node = n0 + rowb + i;
        float4 h0 = make_float4(0.f, 0.f, 0.f, 0.f), h1 = h0;
        if (node < Nn) {
            h0 = *(const float4*)(h + node * H + colb);
            h1 = *(const float4*)(h + node * H + colb + 4);
        }
        float4 v0, v1;
        v0.x = acc[i][0] + h0.x;  v0.y = acc[i][1] + h0.y;
        v0.z = acc[i][2] + h0.z;  v0.w = acc[i][3] + h0.w;
        v1.x = acc[i][4] + h1.x;  v1.y = acc[i][5] + h1.y;
        v1.z = acc[i][6] + h1.z;  v1.w = acc[i][7] + h1.w;
        *(float4*)(Ms + (rowb + i) * MST + colb)     = v0;
        *(float4*)(Ms + (rowb + i) * MST + colb + 4) = v1;
    }
    __syncthreads();

    // -------- LayerNorm: one warp handles 16 rows, lanes span 128 features --------
    const int w = tid >> 5, lane = tid & 31;
    float4 g4  = *(const float4*)(lng + lane * 4);
    float4 bb4 = *(const float4*)(lnb + lane * 4);
#pragma unroll
    for (int rr = 0; rr < 16; ++rr) {
        int r = w * 16 + rr;
        int node = n0 + r;
        if (node >= Nn) break;                      // uniform within warp
        float4 v = *(const float4*)(Ms + r * MST + lane * 4);
        float s  = v.x + v.y + v.z + v.w;
        float s2 = fmaf(v.x, v.x, fmaf(v.y, v.y, fmaf(v.z, v.z, v.w * v.w)));
#pragma unroll
        for (int off = 16; off; off >>= 1) {
            s  += __shfl_xor_sync(0xffffffffu, s,  off);
            s2 += __shfl_xor_sync(0xffffffffu, s2, off);
        }
        float mean = s * (1.f / H);
        float var  = s2 * (1.f / H) - mean * mean;
        float inv  = rsqrtf(var + 1e-5f);
        float4 o;
        o.x = (v.x - mean) * inv * g4.x + bb4.x;
        o.y = (v.y - mean) * inv * g4.y + bb4.y;
        o.z = (v.z - mean) * inv * g4.z + bb4.z;
        o.w = (v.w - mean) * inv * g4.w + bb4.w;
        *(float4*)(h + node * H + lane * 4) = o;
    }
}

// ---------------- launcher ----------------
extern "C" void kernel_launch(void* const* d_in, const int* in_sizes, int n_in,
                              void* d_out, int out_size) {
    const float* x    = (const float*)d_in[0];
    const float* pos  = (const float*)d_in[1];
    const int*   ei   = (const int*)  d_in[2];
    const float* Win  = (const float*)d_in[3];
    const float* bin  = (const float*)d_in[4];
    const float* We1  = (const float*)d_in[5];
    const float* be1  = (const float*)d_in[6];
    const float* We2  = (const float*)d_in[7];
    const float* be2  = (const float*)d_in[8];
    const float* We3  = (const float*)d_in[9];
    const float* be3  = (const float*)d_in[10];
    const float* Wn1  = (const float*)d_in[11];
    const float* bn1  = (const float*)d_in[12];
    const float* Wn2  = (const float*)d_in[13];
    const float* bn2  = (const float*)d_in[14];
    const float* Wn3  = (const float*)d_in[15];
    const float* bn3  = (const float*)d_in[16];
    const float* lng  = (const float*)d_in[17];
    const float* lnb  = (const float*)d_in[18];

    float* h = (float*)d_out;                 // h lives in d_out the whole time
    const int* erow = ei;
    const int* ecol = ei + Ee;

    cudaFuncSetAttribute(k_edge, cudaFuncAttributeMaxDynamicSharedMemorySize, SMEM_BYTES);
    cudaFuncSetAttribute(k_node, cudaFuncAttributeMaxDynamicSharedMemorySize, SMEM_BYTES);

    k_eattr<<<(Ee + 255) / 256, 256>>>(pos, erow, ecol);
    k_h0<<<Nn, H>>>(x, Win, bin, h);

    for (int l = 0; l < 4; ++l) {
        k_zero<<<(Nn * H / 4) / 256, 256>>>();
        k_edge<<<Ee / TILE, 256, SMEM_BYTES>>>(h, erow, ecol,
            We1 + (size_t)l * KE1 * H, be1 + l * H,
            We2 + (size_t)l * H * H,   be2 + l * H,
            We3 + (size_t)l * H * H,   be3 + l * H);
        k_node<<<(Nn + TILE - 1) / TILE, 256, SMEM_BYTES>>>(h,
            Wn1 + (size_t)l * KN1 * H, bn1 + l * H,
            Wn2 + (size_t)l * H * H,   bn2 + l * H,
            Wn3 + (size_t)l * H * H,   bn3 + l * H,
            lng + l * H, lnb + l * H);
    }
}

// round 15
// speedup vs baseline: 2.3621x; 2.3621x over previous
#include <cuda_runtime.h>
#include <cuda_bf16.h>
#include <math.h>
#include <stdint.h>

// ---------------- problem constants ----------------
constexpr int Nn   = 50000;
constexpr int Ee   = 800000;
constexpr int H    = 128;
constexpr int KN1  = 256;
constexpr int TILE = 128;

// ---------------- mma-path smem layout ----------------
constexpr int ASTR   = 136;                 // bf16 elems per A row (odd 16B stride)
constexpr int ABYTES = 128 * ASTR * 2;      // 34816 per plane
constexpr int BSTR   = 136;
constexpr int BBYTES = 64 * BSTR * 2;       // 17408 per plane
constexpr int BS0    = 2 * ABYTES;          // Bs region starts after As hi/lo
constexpr int DSM_BYTES = 2 * ABYTES + 4 * BBYTES;   // 139264 (As hi/lo + 2 slots x B hi/lo)

// ---------------- scratch (device globals: no allocs allowed) ----------------
__device__ __align__(16) __nv_bfloat16 g_whi[(size_t)4 * 576 * 128];
__device__ __align__(16) __nv_bfloat16 g_wlo[(size_t)4 * 576 * 128];
__device__ float g_agg[(size_t)Nn * H];
__device__ float g_ea [(size_t)Ee * 4];

// ---------------- PTX helpers (all plain sm_80+ ISA, no 'a' features) ----------------
__device__ __forceinline__ uint32_t smaddr(const void* p) {
    uint32_t a;
    asm("{ .reg .u64 t; cvta.to.shared.u64 t, %1; cvt.u32.u64 %0, t; }" : "=r"(a) : "l"(p));
    return a;
}
__device__ __forceinline__ void sts32(uint32_t a, uint32_t v) {
    asm volatile("st.shared.b32 [%0], %1;" :: "r"(a), "r"(v) : "memory");
}
__device__ __forceinline__ void ldmx4(uint32_t r[4], uint32_t addr) {
    asm volatile("ldmatrix.sync.aligned.m8n8.x4.shared.b16 {%0,%1,%2,%3}, [%4];"
                 : "=r"(r[0]), "=r"(r[1]), "=r"(r[2]), "=r"(r[3]) : "r"(addr));
}
__device__ __forceinline__ void ldmx4t(uint32_t* r, uint32_t addr) {
    asm volatile("ldmatrix.sync.aligned.m8n8.x4.trans.shared.b16 {%0,%1,%2,%3}, [%4];"
                 : "=r"(r[0]), "=r"(r[1]), "=r"(r[2]), "=r"(r[3]) : "r"(addr));
}
__device__ __forceinline__ void mma16816(float* c, const uint32_t a[4],
                                         uint32_t b0, uint32_t b1) {
    asm volatile("mma.sync.aligned.m16n8k16.row.col.f32.bf16.bf16.f32 "
                 "{%0,%1,%2,%3},{%4,%5,%6,%7},{%8,%9},{%0,%1,%2,%3};"
                 : "+f"(c[0]), "+f"(c[1]), "+f"(c[2]), "+f"(c[3])
                 : "r"(a[0]), "r"(a[1]), "r"(a[2]), "r"(a[3]), "r"(b0), "r"(b1));
}

__device__ __forceinline__ uint32_t pack_hi(float v0, float v1, float& r0, float& r1) {
    __nv_bfloat16 h0 = __float2bfloat16(v0), h1 = __float2bfloat16(v1);
    r0 = v0 - __bfloat162float(h0);
    r1 = v1 - __bfloat162float(h1);
    return (uint32_t)__bfloat16_as_ushort(h0) | ((uint32_t)__bfloat16_as_ushort(h1) << 16);
}
__device__ __forceinline__ uint32_t pack_lo(float r0, float r1) {
    return (uint32_t)__bfloat16_as_ushort(__float2bfloat16(r0)) |
           ((uint32_t)__bfloat16_as_ushort(__float2bfloat16(r1)) << 16);
}

// prefetch one 64-row weight chunk (hi+lo planes) into Bs slot via cp.async
__device__ __forceinline__ void prefB(uint32_t base, const __nv_bfloat16* whi,
                                      const __nv_bfloat16* wlo, int g, int slot, int tid) {
    uint32_t bH = base + BS0 + (uint32_t)slot * (2 * BBYTES);
    uint32_t bL = bH + BBYTES;
#pragma unroll
    for (int pl = 0; pl < 2; ++pl) {
        const __nv_bfloat16* src = pl ? wlo : whi;
        uint32_t dstb = pl ? bL : bH;
#pragma unroll
        for (int it = 0; it < 2; ++it) {
            int v = it * 512 + tid;                  // 1024 16B vectors per plane
            int row = v >> 4, seg = v & 15;
            uint32_t dst = dstb + (uint32_t)(row * BSTR + seg * 8) * 2;
            const void* s = src + (size_t)(g * 64 + row) * 128 + seg * 8;
            asm volatile("cp.async.cg.shared.global [%0], [%1], 16;"
                         :: "r"(dst), "l"(s) : "memory");
        }
    }
}

// relu(acc + bias) -> bf16 hi/lo split -> store into As planes; zero acc
__device__ __forceinline__ void epi_store(uint32_t asH, uint32_t asL,
                                          const float* bs, int m0, int n0,
                                          int lane, float acc[8][4]) {
    const int r0  = m0 + (lane >> 2);
    const int c00 = n0 + (lane & 3) * 2;
#pragma unroll
    for (int t = 0; t < 8; ++t) {
        int col = c00 + t * 8;
        float v0 = fmaxf(acc[t][0] + bs[col],     0.f);
        float v1 = fmaxf(acc[t][1] + bs[col + 1], 0.f);
        float v2 = fmaxf(acc[t][2] + bs[col],     0.f);
        float v3 = fmaxf(acc[t][3] + bs[col + 1], 0.f);
        float q0, q1;
        uint32_t w = pack_hi(v0, v1, q0, q1);
        uint32_t o0 = (uint32_t)(r0 * ASTR + col) * 2;
        sts32(asH + o0, w);
        sts32(asL + o0, pack_lo(q0, q1));
        w = pack_hi(v2, v3, q0, q1);
        uint32_t o1 = (uint32_t)((r0 + 8) * ASTR + col) * 2;
        sts32(asH + o1, w);
        sts32(asL + o1, pack_lo(q0, q1));
        acc[t][0] = acc[t][1] = acc[t][2] = acc[t][3] = 0.f;
    }
}

// ---------------- weight prep: transpose + bf16 split, once per call ----------------
// packed k-rows: [0,320)=We1 (padded), [320,448)=We2, [448,576)=We3
__global__ void k_wprep(const float* __restrict__ We1, const float* __restrict__ We2,
                        const float* __restrict__ We3) {
    int idx = blockIdx.x * 256 + threadIdx.x;
    if (idx >= 4 * 576 * 128) return;
    int n  = idx & 127;
    int t  = idx >> 7;
    int kk = t % 576, l = t / 576;
    float v = 0.f;
    if (kk < 320)      { if (kk < 263) v = We1[((size_t)l * 263 + kk) * H + n]; }
    else if (kk < 448) v = We2[((size_t)l * H + (kk - 320)) * H + n];
    else               v = We3[((size_t)l * H + (kk - 448)) * H + n];
    __nv_bfloat16 hi = __float2bfloat16(v);
    __nv_bfloat16 lo = __float2bfloat16(v - __bfloat162float(hi));
    size_t o = ((size_t)l * 576 + kk) * 128 + n;
    g_whi[o] = hi;
    g_wlo[o] = lo;
}

// ---------------- prologue kernels ----------------
__global__ void k_eattr(const float* __restrict__ pos,
                        const int* __restrict__ erow, const int* __restrict__ ecol) {
    int e = blockIdx.x * blockDim.x + threadIdx.x;
    if (e >= Ee) return;
    int r = erow[e], c = ecol[e];
    float dx = pos[c * 3 + 0] - pos[r * 3 + 0];
    float dy = pos[c * 3 + 1] - pos[r * 3 + 1];
    float dz = pos[c * 3 + 2] - pos[r * 3 + 2];
    float d = sqrtf(dx * dx + dy * dy + dz * dz);
    *(float4*)(g_ea + (size_t)e * 4) = make_float4(dx, dy, dz, d);
}

__global__ void k_h0(const float* __restrict__ x, const float* __restrict__ Win,
                     const float* __restrict__ bin, float* __restrict__ h) {
    __shared__ float xs[16];
    int n = blockIdx.x, j = threadIdx.x;
    if (j < 16) xs[j] = x[n * 16 + j];
    __syncthreads();
    float a = bin[j];
#pragma unroll
    for (int k = 0; k < 16; ++k) a = fmaf(xs[k], Win[k * H + j], a);
    h[n * H + j] = a;
}

__global__ void k_zero() {
    int i = blockIdx.x * blockDim.x + threadIdx.x;
    ((float4*)g_agg)[i] = make_float4(0.f, 0.f, 0.f, 0.f);
}

// ---------------- HMMA fused edge MLP (3 layers) + atomic segment-sum ----------------
// 512 threads = 16 warps; warp tile 16(m) x 64(n); 9 weight chunks of K=64:
//   g 0..4 -> layer1 (K padded 320), g 5,6 -> layer2, g 7,8 -> layer3
__global__ void __launch_bounds__(512, 1)
k_edge(const float* __restrict__ h, const int* __restrict__ erow,
       const int* __restrict__ ecol, int lay,
       const float* __restrict__ b1, const float* __restrict__ b2,
       const float* __restrict__ b3) {
    extern __shared__ char dsm[];
    __shared__ int   ecolS[TILE], erowS[TILE];
    __shared__ float b1s[H], b2s[H], b3s[H];

    const int tid = threadIdx.x, wid = tid >> 5, lane = tid & 31;
    const int e0  = blockIdx.x * TILE;
    const uint32_t base = smaddr(dsm);
    const uint32_t asH = base, asL = base + ABYTES;

    if (tid < 128)      { ecolS[tid] = ecol[e0 + tid];             b1s[tid] = b1[tid]; }
    else if (tid < 256) { erowS[tid - 128] = erow[e0 + tid - 128]; b2s[tid - 128] = b2[tid - 128]; }
    else if (tid < 384) { b3s[tid - 256] = b3[tid - 256]; }

    const int m0 = (wid & 7) * 16, n0 = (wid >> 3) * 64;
    const int lr = lane & 15, lc = lane >> 4;
    const uint32_t aOffH = asH + (uint32_t)((m0 + lr) * ASTR + lc * 8) * 2;
    const uint32_t aOffL = asL + (uint32_t)((m0 + lr) * ASTR + lc * 8) * 2;
    const uint32_t bOff  = (uint32_t)(lr * BSTR + n0 + lc * 8) * 2;

    const __nv_bfloat16* whi = g_whi + (size_t)lay * 576 * 128;
    const __nv_bfloat16* wlo = g_wlo + (size_t)lay * 576 * 128;

    float acc[8][4];
#pragma unroll
    for (int t = 0; t < 8; ++t)
#pragma unroll
        for (int j = 0; j < 4; ++j) acc[t][j] = 0.f;

    prefB(base, whi, wlo, 0, 0, tid);
    asm volatile("cp.async.commit_group;" ::: "memory");

    for (int g = 0; g < 9; ++g) {
        __syncthreads();                       // closes previous mma reads of As / Bs slot
        if (g < 5) {
            // gather + bf16-split A chunk g (layer-1 input, K rows g*64..g*64+63)
            const int k0 = g * 64;
#pragma unroll
            for (int it = 0; it < 8; ++it) {
                int p  = it * 512 + tid;
                int e  = p >> 5;
                int kk = (p & 31) * 2;
                int col = ecolS[e], row = erowS[e];
                float v0 = 0.f, v1 = 0.f;
                if (k0 < 128) {
                    float2 t2 = *(const float2*)(h + (size_t)col * H + k0 + kk);
                    v0 = t2.x; v1 = t2.y;
                } else if (k0 < 256) {
                    float2 t2 = *(const float2*)(h + (size_t)row * H + (k0 - 128) + kk);
                    v0 = t2.x; v1 = t2.y;
                } else {
                    if (kk == 0)      { v0 = g_ea[(size_t)(e0 + e) * 4 + 0]; v1 = g_ea[(size_t)(e0 + e) * 4 + 1]; }
                    else if (kk == 2) { v0 = g_ea[(size_t)(e0 + e) * 4 + 2]; v1 = g_ea[(size_t)(e0 + e) * 4 + 3]; }
                    else if (kk == 4) { v0 = h[(size_t)col * H + 3] - h[(size_t)row * H + 3];
                                        v1 = h[(size_t)col * H + 4] - h[(size_t)row * H + 4]; }
                    else if (kk == 6) { v0 = h[(size_t)col * H + 5] - h[(size_t)row * H + 5]; }
                }
                float r0, r1;
                uint32_t w0 = pack_hi(v0, v1, r0, r1);
                uint32_t w1 = pack_lo(r0, r1);
                uint32_t off = (uint32_t)(e * ASTR + kk) * 2;
                sts32(asH + off, w0);
                sts32(asL + off, w1);
            }
        } else if (g == 5) {
            epi_store(asH, asL, b1s, m0, n0, lane, acc);   // layer1 -> As (K=128)
        } else if (g == 7) {
            epi_store(asH, asL, b2s, m0, n0, lane, acc);   // layer2 -> As
        }
        if (g < 8) {
            prefB(base, whi, wlo, g + 1, (g + 1) & 1, tid);
            asm volatile("cp.async.commit_group;" ::: "memory");
            asm volatile("cp.async.wait_group 1;" ::: "memory");   // chunk g ready
        } else {
            asm volatile("cp.async.wait_group 0;" ::: "memory");
        }
        __syncthreads();

        // ---- mma on chunk g ----
        const int acol = (g < 5) ? 0 : ((g - 5) & 1) * 64;
        const uint32_t bH = base + BS0 + (uint32_t)(g & 1) * (2 * BBYTES);
        const uint32_t bL = bH + BBYTES;
#pragma unroll
        for (int ks = 0; ks < 4; ++ks) {
            uint32_t a_h[4], a_l[4], bb[16];
            ldmx4(a_h, aOffH + (uint32_t)(acol + ks * 16) * 2);
            ldmx4(a_l, aOffL + (uint32_t)(acol + ks * 16) * 2);
            uint32_t br = bH + (uint32_t)(ks * 16) * (BSTR * 2) + bOff;
            ldmx4t(bb + 0,  br);
            ldmx4t(bb + 4,  br + 32);
            ldmx4t(bb + 8,  br + 64);
            ldmx4t(bb + 12, br + 96);
#pragma unroll
            for (int t = 0; t < 8; ++t) {
                uint32_t q0 = bb[(t >> 1) * 4 + (t & 1) * 2];
                uint32_t q1 = bb[(t >> 1) * 4 + (t & 1) * 2 + 1];
                mma16816(acc[t], a_h, q0, q1);   // Ahi * Bhi
                mma16816(acc[t], a_l, q0, q1);   // Alo * Bhi
            }
            uint32_t brl = bL + (uint32_t)(ks * 16) * (BSTR * 2) + bOff;
            ldmx4t(bb + 0,  brl);
            ldmx4t(bb + 4,  brl + 32);
            ldmx4t(bb + 8,  brl + 64);
            ldmx4t(bb + 12, brl + 96);
#pragma unroll
            for (int t = 0; t < 8; ++t) {
                mma16816(acc[t], a_h,
                         bb[(t >> 1) * 4 + (t & 1) * 2],
                         bb[(t >> 1) * 4 + (t & 1) * 2 + 1]);   // Ahi * Blo
            }
        }
    }

    // ---- final epilogue: D + b3 -> atomic scatter into g_agg[col] ----
    const int r0  = m0 + (lane >> 2);
    const int c00 = n0 + (lane & 3) * 2;
    const int t0 = ecolS[r0], t1 = ecolS[r0 + 8];
    float* d0 = g_agg + (size_t)t0 * H;
    float* d1 = g_agg + (size_t)t1 * H;
#pragma unroll
    for (int t = 0; t < 8; ++t) {
        int col = c00 + t * 8;
        atomicAdd(d0 + col,     acc[t][0] + b3s[col]);
        atomicAdd(d0 + col + 1, acc[t][1] + b3s[col + 1]);
        atomicAdd(d1 + col,     acc[t][2] + b3s[col]);
        atomicAdd(d1 + col + 1, acc[t][3] + b3s[col + 1]);
    }
}

// ---------------- fp32 node MLP (unchanged passing path) ----------------
constexpr int KC   = 64;
constexpr int MST  = 132;
constexpr int SMEM_FLOATS = TILE * MST + KC * H;
constexpr int SMEM_BYTES  = SMEM_FLOATS * 4;

__device__ __forceinline__ void init_bias(const float* __restrict__ b, int colb,
                                          float acc[8][8]) {
    float4 c0 = *(const float4*)(b + colb);
    float4 c1 = *(const float4*)(b + colb + 4);
    float bb[8] = {c0.x, c0.y, c0.z, c0.w, c1.x, c1.y, c1.z, c1.w};
#pragma unroll
    for (int i = 0; i < 8; ++i)
#pragma unroll
        for (int j = 0; j < 8; ++j) acc[i][j] = bb[j];
}

__device__ __forceinline__ void mma_chunk(const float* __restrict__ A, int astride,
                                          const float* __restrict__ Bs,
                                          int rowb, int colb, float acc[8][8]) {
#pragma unroll 4
    for (int k = 0; k < KC; ++k) {
        float a[8];
#pragma unroll
        for (int i = 0; i < 8; ++i) a[i] = A[(rowb + i) * astride + k];
        float4 b0 = *(const float4*)(Bs + k * H + colb);
        float4 b1 = *(const float4*)(Bs + k * H + colb + 4);
        float b[8] = {b0.x, b0.y, b0.z, b0.w, b1.x, b1.y, b1.z, b1.w};
#pragma unroll
        for (int i = 0; i < 8; ++i)
#pragma unroll
            for (int j = 0; j < 8; ++j)
                acc[i][j] = fmaf(a[i], b[j], acc[i][j]);
    }
}

__device__ __forceinline__ void load_B(float* __restrict__ Bs,
                                       const float* __restrict__ W,
                                       int k0, int K, int tid) {
#pragma unroll
    for (int it = 0; it < (KC * H) / 256; ++it) {
        int idx = it * 256 + tid;
        int f = idx & (H - 1);
        int k = idx >> 7;
        int kg = k0 + k;
        Bs[k * H + f] = (kg < K) ? W[kg * H + f] : 0.f;
    }
}

template <bool RELU>
__device__ __forceinline__ void store_tile(float* __restrict__ Ms, int rowb, int colb,
                                           const float acc[8][8]) {
#pragma unroll
    for (int i = 0; i < 8; ++i) {
        float4 v0, v1;
        v0.x = RELU ? fmaxf(acc[i][0], 0.f) : acc[i][0];
        v0.y = RELU ? fmaxf(acc[i][1], 0.f) : acc[i][1];
        v0.z = RELU ? fmaxf(acc[i][2], 0.f) : acc[i][2];
        v0.w = RELU ? fmaxf(acc[i][3], 0.f) : acc[i][3];
        v1.x = RELU ? fmaxf(acc[i][4], 0.f) : acc[i][4];
        v1.y = RELU ? fmaxf(acc[i][5], 0.f) : acc[i][5];
        v1.z = RELU ? fmaxf(acc[i][6], 0.f) : acc[i][6];
        v1.w = RELU ? fmaxf(acc[i][7], 0.f) : acc[i][7];
        *(float4*)(Ms + (rowb + i) * MST + colb)     = v0;
        *(float4*)(Ms + (rowb + i) * MST + colb + 4) = v1;
    }
}

__device__ __forceinline__ void hidden_layer(const float* __restrict__ Ms,
                                             float* __restrict__ Bs,
                                             const float* __restrict__ W,
                                             const float* __restrict__ b,
                                             int rowb, int colb, int tid,
                                             float acc[8][8]) {
    init_bias(b, colb, acc);
#pragma unroll
    for (int c = 0; c < 2; ++c) {
        if (c) __syncthreads();
        load_B(Bs, W, c * KC, H, tid);
        __syncthreads();
        mma_chunk(Ms + c * KC, MST, Bs, rowb, colb, acc);
    }
}

__global__ void __launch_bounds__(256, 2)
k_node(float* __restrict__ h,
       const float* __restrict__ W1, const float* __restrict__ b1,
       const float* __restrict__ W2, const float* __restrict__ b2,
       const float* __restrict__ W3, const float* __restrict__ b3,
       const float* __restrict__ lng, const float* __restrict__ lnb) {
    extern __shared__ float sm[];
    float* Ms = sm;
    float* Ag = sm;
    float* Bs = sm + TILE * MST;

    const int tid  = threadIdx.x;
    const int tx   = tid & 15, ty = tid >> 4;
    const int rowb = ty * 8, colb = tx * 8;
    const int n0   = blockIdx.x * TILE;

    float acc[8][8];

    init_bias(b1, colb, acc);
    for (int k0 = 0; k0 < KN1; k0 += KC) {
        if (k0) __syncthreads();
#pragma unroll 4
        for (int it = 0; it < (TILE * KC) / 256; ++it) {
            int idx = it * 256 + tid;
            int e = idx >> 6;
            int k = idx & (KC - 1);
            int kg = k0 + k;
            int node = n0 + e;
            if (node >= Nn) node = Nn - 1;
            float v = (kg < 128) ? h[node * H + kg]
                                 : g_agg[(size_t)node * H + (kg - 128)];
            Ag[e * KC + k] = v;
        }
        load_B(Bs, W1, k0, KN1, tid);
        __syncthreads();
        mma_chunk(Ag, KC, Bs, rowb, colb, acc);
    }
    __syncthreads();
    store_tile<true>(Ms, rowb, colb, acc);
    __syncthreads();

    hidden_layer(Ms, Bs, W2, b2, rowb, colb, tid, acc);
    __syncthreads();
    store_tile<true>(Ms, rowb, colb, acc);
    __syncthreads();

    hidden_layer(Ms, Bs, W3, b3, rowb, colb, tid, acc);
    __syncthreads();
#pragma unroll
    for (int i = 0; i < 8; ++i) {
        int node = n0 + rowb + i;
        float4 h0 = make_float4(0.f, 0.f, 0.f, 0.f), h1 = h0;
        if (node < Nn) {
            h0 = *(const float4*)(h + node * H + colb);
            h1 = *(const float4*)(h + node * H + colb + 4);
        }
        float4 v0, v1;
        v0.x = acc[i][0] + h0.x;  v0.y = acc[i][1] + h0.y;
        v0.z = acc[i][2] + h0.z;  v0.w = acc[i][3] + h0.w;
        v1.x = acc[i][4] + h1.x;  v1.y = acc[i][5] + h1.y;
        v1.z = acc[i][6] + h1.z;  v1.w = acc[i][7] + h1.w;
        *(float4*)(Ms + (rowb + i) * MST + colb)     = v0;
        *(float4*)(Ms + (rowb + i) * MST + colb + 4) = v1;
    }
    __syncthreads();

    const int w = tid >> 5, lane = tid & 31;
    float4 g4  = *(const float4*)(lng + lane * 4);
    float4 bb4 = *(const float4*)(lnb + lane * 4);
#pragma unroll
    for (int rr = 0; rr < 16; ++rr) {
        int r = w * 16 + rr;
        int node = n0 + r;
        if (node >= Nn) break;
        float4 v = *(const float4*)(Ms + r * MST + lane * 4);
        float s  = v.x + v.y + v.z + v.w;
        float s2 = fmaf(v.x, v.x, fmaf(v.y, v.y, fmaf(v.z, v.z, v.w * v.w)));
#pragma unroll
        for (int off = 16; off; off >>= 1) {
            s  += __shfl_xor_sync(0xffffffffu, s,  off);
            s2 += __shfl_xor_sync(0xffffffffu, s2, off);
        }
        float mean = s * (1.f / H);
        float var  = s2 * (1.f / H) - mean * mean;
        float inv  = rsqrtf(var + 1e-5f);
        float4 o;
        o.x = (v.x - mean) * inv * g4.x + bb4.x;
        o.y = (v.y - mean) * inv * g4.y + bb4.y;
        o.z = (v.z - mean) * inv * g4.z + bb4.z;
        o.w = (v.w - mean) * inv * g4.w + bb4.w;
        *(float4*)(h + node * H + lane * 4) = o;
    }
}

// ---------------- launcher ----------------
extern "C" void kernel_launch(void* const* d_in, const int* in_sizes, int n_in,
                              void* d_out, int out_size) {
    const float* x    = (const float*)d_in[0];
    const float* pos  = (const float*)d_in[1];
    const int*   ei   = (const int*)  d_in[2];
    const float* Win  = (const float*)d_in[3];
    const float* bin  = (const float*)d_in[4];
    const float* We1  = (const float*)d_in[5];
    const float* be1  = (const float*)d_in[6];
    const float* We2  = (const float*)d_in[7];
    const float* be2  = (const float*)d_in[8];
    const float* We3  = (const float*)d_in[9];
    const float* be3  = (const float*)d_in[10];
    const float* Wn1  = (const float*)d_in[11];
    const float* bn1  = (const float*)d_in[12];
    const float* Wn2  = (const float*)d_in[13];
    const float* bn2  = (const float*)d_in[14];
    const float* Wn3  = (const float*)d_in[15];
    const float* bn3  = (const float*)d_in[16];
    const float* lng  = (const float*)d_in[17];
    const float* lnb  = (const float*)d_in[18];

    float* h = (float*)d_out;
    const int* erow = ei;
    const int* ecol = ei + Ee;

    cudaFuncSetAttribute(k_edge, cudaFuncAttributeMaxDynamicSharedMemorySize, DSM_BYTES);
    cudaFuncSetAttribute(k_node, cudaFuncAttributeMaxDynamicSharedMemorySize, SMEM_BYTES);

    k_wprep<<<(4 * 576 * 128 + 255) / 256, 256>>>(We1, We2, We3);
    k_eattr<<<(Ee + 255) / 256, 256>>>(pos, erow, ecol);
    k_h0<<<Nn, H>>>(x, Win, bin, h);

    for (int l = 0; l < 4; ++l) {
        k_zero<<<(Nn * H / 4) / 256, 256>>>();
        k_edge<<<Ee / TILE, 512, DSM_BYTES>>>(h, erow, ecol, l,
            be1 + l * H, be2 + l * H, be3 + l * H);
        k_node<<<(Nn + TILE - 1) / TILE, 256, SMEM_BYTES>>>(h,
            Wn1 + (size_t)l * KN1 * H, bn1 + l * H,
            Wn2 + (size_t)l * H * H,   bn2 + l * H,
            Wn3 + (size_t)l * H * H,   bn3 + l * H,
            lng + l * H, lnb + l * H);
    }
}